// round 13
// baseline (speedup 1.0000x reference)
#include <cuda_runtime.h>
#include <math.h>

#define NMAX 10000
#define EMAX 160000
#define CAP  96
#define NEG_SLOPE 0.2f
#define GAT_EPS 1e-16f

// ---------------- device scratch ----------------
__device__ int      g_ctr[NMAX];                  // ZERO invariant at launch start
__device__ unsigned g_csr[NMAX * CAP];            // src | (maskedBit<<31), bucketed
__device__ __align__(16) float g_h1[NMAX * 64];
__device__ __align__(16) float g_as1[NMAX * 8];
__device__ __align__(16) float g_ad1[NMAX * 8];
__device__ __align__(16) float g_h1a[NMAX * 64];
__device__ __align__(16) float g_vs[8 * 64];
__device__ __align__(16) float g_vd[8 * 64];
__device__ __align__(16) float g_as2[NMAX * 8];
__device__ __align__(16) float g_ad2[NMAX * 8];

// ---------------- front-end: CSR fill + layer1 GEMM/attn + prep2 in ONE grid ----
// blocks [0, FB)           : edge fill (vec4 when vec==1, scalar otherwise)
// blocks [FB, FB+GB)       : gemm1 16-row tiles
// block  FB+GB             : prep2
__global__ void k_front(const float* __restrict__ x, const float* __restrict__ W1,
                        const float* __restrict__ asw, const float* __restrict__ adw,
                        const float* __restrict__ W2, const float* __restrict__ as2w,
                        const float* __restrict__ ad2w, const int* __restrict__ ei,
                        int E, int N, int FB, int GB, int vec) {
    int b = blockIdx.x;
    if (b < FB) {
        // ---- fill ----
        int i = b * blockDim.x + threadIdx.x;
        if (vec) {
            int j = i * 4;
            if (j + 3 < E) {
                int4 s4 = ((const int4*)ei)[i];
                int4 d4 = ((const int4*)(ei + E))[i];
                int ss[4] = {s4.x, s4.y, s4.z, s4.w};
                int dd[4] = {d4.x, d4.y, d4.z, d4.w};
                #pragma unroll
                for (int t = 0; t < 4; t++) {
                    int s = ss[t], d = dd[t];
                    if ((unsigned)s >= (unsigned)N || (unsigned)d >= (unsigned)N) continue;
                    unsigned ent = (unsigned)s | ((s == d) ? 0x80000000u : 0u);
                    int pos = atomicAdd(&g_ctr[d], 1);
                    if (pos < CAP) g_csr[d * CAP + pos] = ent;
                }
            } else {
                for (int t = j; t < E; t++) {
                    int s = ei[t], d = ei[E + t];
                    if ((unsigned)s >= (unsigned)N || (unsigned)d >= (unsigned)N) continue;
                    unsigned ent = (unsigned)s | ((s == d) ? 0x80000000u : 0u);
                    int pos = atomicAdd(&g_ctr[d], 1);
                    if (pos < CAP) g_csr[d * CAP + pos] = ent;
                }
            }
        } else {
            if (i < E) {
                int s = ei[i], d = ei[E + i];
                if ((unsigned)s < (unsigned)N && (unsigned)d < (unsigned)N) {
                    unsigned ent = (unsigned)s | ((s == d) ? 0x80000000u : 0u);
                    int pos = atomicAdd(&g_ctr[d], 1);
                    if (pos < CAP) g_csr[d * CAP + pos] = ent;
                }
            }
        }
        return;
    }
    if (b == FB + GB) {
        // ---- prep2: vs[h][k] = sum_c W2[k, h*128+c] * a_src2[h,c] ----
        int tid = threadIdx.x;
        for (int idx = tid; idx < 512; idx += 256) {
            int h = idx >> 6, k = idx & 63;
            const float* wrow = W2 + (size_t)k * 1024 + h * 128;
            const float* sa = as2w + h * 128;
            const float* da = ad2w + h * 128;
            float s = 0.f, d = 0.f;
            #pragma unroll 4
            for (int c = 0; c < 128; c++) {
                float w = wrow[c];
                s = fmaf(w, sa[c], s);
                d = fmaf(w, da[c], d);
            }
            g_vs[h * 64 + k] = s;
            g_vd[h * 64 + k] = d;
        }
        return;
    }
    // ---- gemm1 tile ----
    int tb = b - FB;
    int col  = threadIdx.x & 63;
    int rs   = threadIdx.x >> 6;
    int row0 = tb * 16 + rs * 4;
    const float* xp0 = x + (size_t)min(row0 + 0, N - 1) * 128;
    const float* xp1 = x + (size_t)min(row0 + 1, N - 1) * 128;
    const float* xp2 = x + (size_t)min(row0 + 2, N - 1) * 128;
    const float* xp3 = x + (size_t)min(row0 + 3, N - 1) * 128;
    float a[4] = {0.f, 0.f, 0.f, 0.f};
    #pragma unroll 4
    for (int k = 0; k < 128; k++) {
        float w = W1[k * 64 + col];
        a[0] = fmaf(xp0[k], w, a[0]);
        a[1] = fmaf(xp1[k], w, a[1]);
        a[2] = fmaf(xp2[k], w, a[2]);
        a[3] = fmaf(xp3[k], w, a[3]);
    }
    #pragma unroll
    for (int r = 0; r < 4; r++)
        if (row0 + r < N) g_h1[(size_t)(row0 + r) * 64 + col] = a[r];

    float ws = asw[col], wd = adw[col];
    #pragma unroll
    for (int r = 0; r < 4; r++) {
        float ps = a[r] * ws, pd = a[r] * wd;
        ps += __shfl_down_sync(0xffffffffu, ps, 4);
        pd += __shfl_down_sync(0xffffffffu, pd, 4);
        ps += __shfl_down_sync(0xffffffffu, ps, 2);
        pd += __shfl_down_sync(0xffffffffu, pd, 2);
        ps += __shfl_down_sync(0xffffffffu, ps, 1);
        pd += __shfl_down_sync(0xffffffffu, pd, 1);
        if ((col & 7) == 0 && row0 + r < N) {
            g_as1[(row0 + r) * 8 + (col >> 3)] = ps;
            g_ad1[(row0 + r) * 8 + (col >> 3)] = pd;
        }
    }
}

// one warp per node: layer1 softmax+aggregate (self-loop analytic) + bias + ELU + layer2 dots
__global__ void k_agg1f(const float* __restrict__ b1, int N) {
    int gw = (blockIdx.x * blockDim.x + threadIdx.x) >> 5;
    int lane = threadIdx.x & 31;
    if (gw >= N) return;
    int n = gw;
    int deg = min(g_ctr[n], CAP);
    const unsigned* crow = g_csr + (size_t)n * CAP;
    int myh = lane >> 2;

    float4 AD0 = *(const float4*)(g_ad1 + n * 8);
    float4 AD1 = *(const float4*)(g_ad1 + n * 8 + 4);
    float ad[8] = {AD0.x, AD0.y, AD0.z, AD0.w, AD1.x, AD1.y, AD1.z, AD1.w};
    float4 AN0 = *(const float4*)(g_as1 + n * 8);
    float4 AN1 = *(const float4*)(g_as1 + n * 8 + 4);
    float asn[8] = {AN0.x, AN0.y, AN0.z, AN0.w, AN1.x, AN1.y, AN1.z, AN1.w};

    float m[8], s[8];
    #pragma unroll
    for (int h = 0; h < 8; h++) { m[h] = -INFINITY; s[h] = 0.f; }

    for (int j = lane; j < deg; j += 32) {
        unsigned ent = crow[j];
        int src = (int)(ent & 0x7fffffffu);
        float msk = (ent & 0x80000000u) ? 0.f : 1.f;
        float4 A0 = *(const float4*)(g_as1 + src * 8);
        float4 A1 = *(const float4*)(g_as1 + src * 8 + 4);
        float as_[8] = {A0.x, A0.y, A0.z, A0.w, A1.x, A1.y, A1.z, A1.w};
        #pragma unroll
        for (int h = 0; h < 8; h++) {
            float t = as_[h] + ad[h];
            float e = t > 0.f ? t : NEG_SLOPE * t;
            float nm = fmaxf(m[h], e);
            s[h] = s[h] * __expf(m[h] - nm) + msk * __expf(e - nm);
            m[h] = nm;
        }
    }
    float myM = 0.f, myRS = 0.f, myE = 0.f;
    #pragma unroll
    for (int h = 0; h < 8; h++) {
        float M = m[h];
        #pragma unroll
        for (int o = 16; o > 0; o >>= 1) M = fmaxf(M, __shfl_xor_sync(0xffffffffu, M, o));
        float S = s[h] * __expf(m[h] - M);
        #pragma unroll
        for (int o = 16; o > 0; o >>= 1) S += __shfl_xor_sync(0xffffffffu, S, o);
        float t = asn[h] + ad[h];
        float e = t > 0.f ? t : NEG_SLOPE * t;
        float nm = fmaxf(M, e);
        S = S * __expf(M - nm) + __expf(e - nm);
        M = nm;
        if (h == myh) { myM = M; myRS = 1.f / (S + GAT_EPS); myE = e; }
    }

    int c0 = lane * 2;
    float adh = ad[0];
    #pragma unroll
    for (int h = 1; h < 8; h++) if (h == myh) adh = ad[h];
    float a0 = 0.f, a1 = 0.f;
    int deg4 = (deg + 3) & ~3;
    for (int j4 = 0; j4 < deg4; j4 += 4) {
        #pragma unroll
        for (int u = 0; u < 4; u++) {
            int j = j4 + u;
            unsigned ent = (j < deg) ? crow[j] : (0x80000000u | (unsigned)n);
            int src = (int)(ent & 0x7fffffffu);
            float msk = (ent & 0x80000000u) ? 0.f : 1.f;
            float t = g_as1[src * 8 + myh] + adh;
            float e = t > 0.f ? t : NEG_SLOPE * t;
            float w = msk * __expf(e - myM) * myRS;
            float2 v = *(const float2*)(g_h1 + (size_t)src * 64 + c0);
            a0 = fmaf(v.x, w, a0);
            a1 = fmaf(v.y, w, a1);
        }
    }
    {   // self-loop contribution
        float w = __expf(myE - myM) * myRS;
        float2 v = *(const float2*)(g_h1 + (size_t)n * 64 + c0);
        a0 = fmaf(v.x, w, a0);
        a1 = fmaf(v.y, w, a1);
    }
    float o0 = a0 + b1[c0], o1 = a1 + b1[c0 + 1];
    o0 = o0 > 0.f ? o0 : (__expf(o0) - 1.f);
    o1 = o1 > 0.f ? o1 : (__expf(o1) - 1.f);
    *(float2*)(g_h1a + (size_t)n * 64 + c0) = make_float2(o0, o1);

    #pragma unroll
    for (int h = 0; h < 8; h++) {
        float ps = o0 * g_vs[h * 64 + c0] + o1 * g_vs[h * 64 + c0 + 1];
        float pd = o0 * g_vd[h * 64 + c0] + o1 * g_vd[h * 64 + c0 + 1];
        #pragma unroll
        for (int o = 16; o > 0; o >>= 1) {
            ps += __shfl_xor_sync(0xffffffffu, ps, o);
            pd += __shfl_xor_sync(0xffffffffu, pd, o);
        }
        if (lane == 0) {
            g_as2[n * 8 + h] = ps;
            g_ad2[n * 8 + h] = pd;
        }
    }
}

// ---------------- merged layer-2: attention agg + GEMM + bias + log_softmax ----------------
#define AS_HSTR 68
#define AS_RSTR (8 * AS_HSTR)   // 544
#define ONODES 8
__global__ void __launch_bounds__(256)
k_agg2out(const float* __restrict__ W2, const float* __restrict__ bias,
          float* __restrict__ out, int N) {
    extern __shared__ float sm[];
    float* As = sm;                     // ONODES * 544
    float* O  = sm + ONODES * AS_RSTR;  // ONODES * 1024
    int tid = threadIdx.x, lane = tid & 31, wid = tid >> 5;
    int row0 = blockIdx.x * ONODES;

    // ---- phase A: warp `wid` aggregates node row0+wid across all 8 heads ----
    {
        int n = min(row0 + wid, N - 1);
        int deg = min(g_ctr[n], CAP);
        // restore launch invariant: g_ctr == 0 at next launch start
        if (lane == 0 && row0 + wid < N) g_ctr[n] = 0;
        const unsigned* crow = g_csr + (size_t)n * CAP;
        float4 D0 = *(const float4*)(g_ad2 + n * 8);
        float4 D1 = *(const float4*)(g_ad2 + n * 8 + 4);
        float ad[8] = {D0.x, D0.y, D0.z, D0.w, D1.x, D1.y, D1.z, D1.w};
        float4 SN0 = *(const float4*)(g_as2 + n * 8);
        float4 SN1 = *(const float4*)(g_as2 + n * 8 + 4);
        float asn[8] = {SN0.x, SN0.y, SN0.z, SN0.w, SN1.x, SN1.y, SN1.z, SN1.w};

        float m[8], s[8];
        #pragma unroll
        for (int h = 0; h < 8; h++) { m[h] = -INFINITY; s[h] = 0.f; }
        for (int j = lane; j < deg; j += 32) {
            unsigned ent = crow[j];
            int src = (int)(ent & 0x7fffffffu);
            float msk = (ent & 0x80000000u) ? 0.f : 1.f;
            float4 A0 = *(const float4*)(g_as2 + src * 8);
            float4 A1 = *(const float4*)(g_as2 + src * 8 + 4);
            float as_[8] = {A0.x, A0.y, A0.z, A0.w, A1.x, A1.y, A1.z, A1.w};
            #pragma unroll
            for (int h = 0; h < 8; h++) {
                float t = as_[h] + ad[h];
                float e = t > 0.f ? t : NEG_SLOPE * t;
                float nm = fmaxf(m[h], e);
                s[h] = s[h] * __expf(m[h] - nm) + msk * __expf(e - nm);
                m[h] = nm;
            }
        }
        float M[8], rd[8], eself[8];
        #pragma unroll
        for (int h = 0; h < 8; h++) {
            float Mh = m[h];
            #pragma unroll
            for (int o = 16; o > 0; o >>= 1) Mh = fmaxf(Mh, __shfl_xor_sync(0xffffffffu, Mh, o));
            float Sh = s[h] * __expf(m[h] - Mh);
            #pragma unroll
            for (int o = 16; o > 0; o >>= 1) Sh += __shfl_xor_sync(0xffffffffu, Sh, o);
            float t = asn[h] + ad[h];
            float e = t > 0.f ? t : NEG_SLOPE * t;
            float nm = fmaxf(Mh, e);
            Sh = Sh * __expf(Mh - nm) + __expf(e - nm);
            M[h] = nm;
            rd[h] = 1.f / (Sh + GAT_EPS);
            eself[h] = e;
        }

        int c0 = lane * 2;
        float acc[16];
        #pragma unroll
        for (int i = 0; i < 16; i++) acc[i] = 0.f;

        for (int basej = 0; basej < deg; basej += 32) {
            int cnt = min(32, deg - basej);
            float w8[8];
            int srcl = n;            // lanes >= cnt: valid address, zero weight
            #pragma unroll
            for (int h = 0; h < 8; h++) w8[h] = 0.f;
            if (lane < cnt) {
                unsigned ent = crow[basej + lane];
                srcl = (int)(ent & 0x7fffffffu);
                float msk = (ent & 0x80000000u) ? 0.f : 1.f;
                float4 A0 = *(const float4*)(g_as2 + srcl * 8);
                float4 A1 = *(const float4*)(g_as2 + srcl * 8 + 4);
                float as_[8] = {A0.x, A0.y, A0.z, A0.w, A1.x, A1.y, A1.z, A1.w};
                #pragma unroll
                for (int h = 0; h < 8; h++) {
                    float t = as_[h] + ad[h];
                    float e = t > 0.f ? t : NEG_SLOPE * t;
                    w8[h] = msk * __expf(e - M[h]) * rd[h];
                }
            }
            // MLP-4 gather: padded lanes carry w=0, src=n (exact no-op)
            int cnt4 = (cnt + 3) & ~3;
            for (int j4 = 0; j4 < cnt4; j4 += 4) {
                #pragma unroll
                for (int u = 0; u < 4; u++) {
                    int jj = j4 + u;
                    int src = __shfl_sync(0xffffffffu, srcl, jj);
                    float2 v = *(const float2*)(g_h1a + (size_t)src * 64 + c0);
                    #pragma unroll
                    for (int h = 0; h < 8; h++) {
                        float w = __shfl_sync(0xffffffffu, w8[h], jj);
                        acc[h * 2 + 0] = fmaf(v.x, w, acc[h * 2 + 0]);
                        acc[h * 2 + 1] = fmaf(v.y, w, acc[h * 2 + 1]);
                    }
                }
            }
        }
        {   // self-loop
            float2 v = *(const float2*)(g_h1a + (size_t)n * 64 + c0);
            #pragma unroll
            for (int h = 0; h < 8; h++) {
                float w = __expf(eself[h] - M[h]) * rd[h];
                acc[h * 2 + 0] = fmaf(v.x, w, acc[h * 2 + 0]);
                acc[h * 2 + 1] = fmaf(v.y, w, acc[h * 2 + 1]);
            }
        }
        #pragma unroll
        for (int h = 0; h < 8; h++) {
            As[wid * AS_RSTR + h * AS_HSTR + c0]     = acc[h * 2 + 0];
            As[wid * AS_RSTR + h * AS_HSTR + c0 + 1] = acc[h * 2 + 1];
        }
    }
    __syncthreads();

    // ---- phase B: GEMM (8 rows x 1024 cols, K=64 per head) + bias ----
    // lane owns 4 CONTIGUOUS cols -> one LDG.128 of W2 per k (was 4x LDG.32)
    {
        int hg = wid;                 // 8 warps = 8 heads
        int cb = hg * 128 + lane * 4; // contiguous quad
        float4 acc2[8];
        #pragma unroll
        for (int r = 0; r < 8; r++) acc2[r] = make_float4(0.f, 0.f, 0.f, 0.f);
        const float* Wp = W2 + cb;
        const float* Ap = As + hg * AS_HSTR;
        #pragma unroll 4
        for (int k = 0; k < 64; k++) {
            float4 w = *(const float4*)(Wp + (size_t)k * 1024);
            #pragma unroll
            for (int r = 0; r < 8; r++) {
                float a = Ap[r * AS_RSTR + k];
                acc2[r].x = fmaf(a, w.x, acc2[r].x);
                acc2[r].y = fmaf(a, w.y, acc2[r].y);
                acc2[r].z = fmaf(a, w.z, acc2[r].z);
                acc2[r].w = fmaf(a, w.w, acc2[r].w);
            }
        }
        float4 bb = *(const float4*)(bias + cb);
        #pragma unroll
        for (int r = 0; r < 8; r++) {
            float4 o;
            o.x = acc2[r].x + bb.x;
            o.y = acc2[r].y + bb.y;
            o.z = acc2[r].z + bb.z;
            o.w = acc2[r].w + bb.w;
            *(float4*)(O + r * 1024 + cb) = o;
        }
    }
    __syncthreads();

    // ---- phase C: log_softmax, warp per row ----
    int n2 = row0 + wid;
    if (n2 < N) {
        const float4* Or = (const float4*)(O + wid * 1024);
        float m = -INFINITY;
        #pragma unroll
        for (int i = 0; i < 8; i++) {
            float4 xv = Or[lane + i * 32];
            m = fmaxf(m, fmaxf(fmaxf(xv.x, xv.y), fmaxf(xv.z, xv.w)));
        }
        #pragma unroll
        for (int o = 16; o > 0; o >>= 1) m = fmaxf(m, __shfl_xor_sync(0xffffffffu, m, o));
        float s = 0.f;
        #pragma unroll
        for (int i = 0; i < 8; i++) {
            float4 xv = Or[lane + i * 32];
            s += __expf(xv.x - m) + __expf(xv.y - m) + __expf(xv.z - m) + __expf(xv.w - m);
        }
        #pragma unroll
        for (int o = 16; o > 0; o >>= 1) s += __shfl_xor_sync(0xffffffffu, s, o);
        float lse = m + logf(s);
        float4* op = (float4*)(out + (size_t)n2 * 1024);
        #pragma unroll
        for (int i = 0; i < 8; i++) {
            float4 xv = Or[lane + i * 32];
            op[lane + i * 32] = make_float4(xv.x - lse, xv.y - lse, xv.z - lse, xv.w - lse);
        }
    }
}

// ---------------- launcher: 3 serial graph nodes, no streams/events ----------------
extern "C" void kernel_launch(void* const* d_in, const int* in_sizes, int n_in,
                              void* d_out, int out_size) {
    const float* x   = (const float*)d_in[0];
    const int*   ei  = (const int*)d_in[1];
    const float* W1  = (const float*)d_in[2];
    const float* aS1 = (const float*)d_in[3];
    const float* aD1 = (const float*)d_in[4];
    const float* b1  = (const float*)d_in[5];
    const float* W2  = (const float*)d_in[6];
    const float* aS2 = (const float*)d_in[7];
    const float* aD2 = (const float*)d_in[8];
    const float* b2  = (const float*)d_in[9];
    float*       out = (float*)d_out;

    int N = in_sizes[0] / 128;
    int E = in_sizes[1] / 2;

    int vec = ((E & 3) == 0) ? 1 : 0;
    int FB = vec ? (E / 4 + 255) / 256 : (E + 255) / 256;
    int GB = (N + 15) / 16;

    static const int SMEM2 = (ONODES * AS_RSTR + ONODES * 1024) * 4;   // 50176
    static bool init = false;
    if (!init) {
        cudaFuncSetAttribute(k_agg2out, cudaFuncAttributeMaxDynamicSharedMemorySize, SMEM2);
        init = true;
    }

    // g_ctr is zero here: zero-initialized at module load, and re-zeroed by
    // k_agg2out at the end of every launch (graph-replay invariant).
    k_front  <<<FB + GB + 1, 256>>>(x, W1, aS1, aD1, W2, aS2, aD2, ei, E, N, FB, GB, vec);
    k_agg1f  <<<(N * 32 + 255) / 256, 256>>>(b1, N);
    k_agg2out<<<(N + ONODES - 1) / ONODES, 256, SMEM2>>>(W2, b2, out, N);
}

// round 14
// speedup vs baseline: 1.1455x; 1.1455x over previous
#include <cuda_runtime.h>
#include <math.h>

#define NMAX 10000
#define EMAX 160000
#define CAP  96
#define NEG_SLOPE 0.2f
#define GAT_EPS 1e-16f

// ---------------- device scratch ----------------
__device__ int      g_ctr[NMAX];
__device__ unsigned g_csr[NMAX * CAP];            // src | (maskedBit<<31), bucketed
__device__ __align__(16) float g_h1[NMAX * 64];
__device__ __align__(16) float g_as1[NMAX * 8];
__device__ __align__(16) float g_ad1[NMAX * 8];
__device__ __align__(16) float g_h1a[NMAX * 64];
__device__ __align__(16) float g_vs[8 * 64];
__device__ __align__(16) float g_vd[8 * 64];
__device__ __align__(16) float g_as2[NMAX * 8];
__device__ __align__(16) float g_ad2[NMAX * 8];

// ---------------- CSR fill (bucketed, no scan) ----------------
__global__ void k_fill4(const int* __restrict__ ei, int E, int N) {
    int i = blockIdx.x * blockDim.x + threadIdx.x;
    int j = i * 4;
    if (j + 3 < E) {
        int4 s4 = ((const int4*)ei)[i];
        int4 d4 = ((const int4*)(ei + E))[i];
        int ss[4] = {s4.x, s4.y, s4.z, s4.w};
        int dd[4] = {d4.x, d4.y, d4.z, d4.w};
        #pragma unroll
        for (int t = 0; t < 4; t++) {
            int s = ss[t], d = dd[t];
            if ((unsigned)s >= (unsigned)N || (unsigned)d >= (unsigned)N) continue;
            unsigned ent = (unsigned)s | ((s == d) ? 0x80000000u : 0u);
            int pos = atomicAdd(&g_ctr[d], 1);
            if (pos < CAP) g_csr[d * CAP + pos] = ent;
        }
    } else {
        for (int t = j; t < E; t++) {
            int s = ei[t], d = ei[E + t];
            if ((unsigned)s >= (unsigned)N || (unsigned)d >= (unsigned)N) continue;
            unsigned ent = (unsigned)s | ((s == d) ? 0x80000000u : 0u);
            int pos = atomicAdd(&g_ctr[d], 1);
            if (pos < CAP) g_csr[d * CAP + pos] = ent;
        }
    }
}
__global__ void k_fill(const int* __restrict__ ei, int E, int N) {
    int i = blockIdx.x * blockDim.x + threadIdx.x;
    if (i >= E) return;
    int s = ei[i];
    int d = ei[E + i];
    if ((unsigned)s >= (unsigned)N || (unsigned)d >= (unsigned)N) return;
    unsigned ent = (unsigned)s | ((s == d) ? 0x80000000u : 0u);
    int pos = atomicAdd(&g_ctr[d], 1);
    if (pos < CAP) g_csr[d * CAP + pos] = ent;
}

// ---------------- layer 1 GEMM + attn dots + (folded) prep2 ----------------
__global__ void k_gemm1f(const float* __restrict__ x, const float* __restrict__ W1,
                         const float* __restrict__ asw, const float* __restrict__ adw,
                         const float* __restrict__ W2, const float* __restrict__ as2w,
                         const float* __restrict__ ad2w, int N) {
    if (blockIdx.x == gridDim.x - 1) {
        int tid = threadIdx.x;
        for (int idx = tid; idx < 512; idx += 256) {
            int h = idx >> 6, k = idx & 63;
            const float* wrow = W2 + (size_t)k * 1024 + h * 128;
            const float* sa = as2w + h * 128;
            const float* da = ad2w + h * 128;
            float s = 0.f, d = 0.f;
            #pragma unroll 4
            for (int c = 0; c < 128; c++) {
                float w = wrow[c];
                s = fmaf(w, sa[c], s);
                d = fmaf(w, da[c], d);
            }
            g_vs[h * 64 + k] = s;
            g_vd[h * 64 + k] = d;
        }
        return;
    }
    int col  = threadIdx.x & 63;
    int rs   = threadIdx.x >> 6;
    int row0 = blockIdx.x * 16 + rs * 4;
    const float* xp0 = x + (size_t)min(row0 + 0, N - 1) * 128;
    const float* xp1 = x + (size_t)min(row0 + 1, N - 1) * 128;
    const float* xp2 = x + (size_t)min(row0 + 2, N - 1) * 128;
    const float* xp3 = x + (size_t)min(row0 + 3, N - 1) * 128;
    float a[4] = {0.f, 0.f, 0.f, 0.f};
    #pragma unroll 4
    for (int k = 0; k < 128; k++) {
        float w = W1[k * 64 + col];
        a[0] = fmaf(xp0[k], w, a[0]);
        a[1] = fmaf(xp1[k], w, a[1]);
        a[2] = fmaf(xp2[k], w, a[2]);
        a[3] = fmaf(xp3[k], w, a[3]);
    }
    #pragma unroll
    for (int r = 0; r < 4; r++)
        if (row0 + r < N) g_h1[(size_t)(row0 + r) * 64 + col] = a[r];

    float ws = asw[col], wd = adw[col];
    #pragma unroll
    for (int r = 0; r < 4; r++) {
        float ps = a[r] * ws, pd = a[r] * wd;
        ps += __shfl_down_sync(0xffffffffu, ps, 4);
        pd += __shfl_down_sync(0xffffffffu, pd, 4);
        ps += __shfl_down_sync(0xffffffffu, ps, 2);
        pd += __shfl_down_sync(0xffffffffu, pd, 2);
        ps += __shfl_down_sync(0xffffffffu, ps, 1);
        pd += __shfl_down_sync(0xffffffffu, pd, 1);
        if ((col & 7) == 0 && row0 + r < N) {
            g_as1[(row0 + r) * 8 + (col >> 3)] = ps;
            g_ad1[(row0 + r) * 8 + (col >> 3)] = pd;
        }
    }
}

// one warp per node: layer1 softmax+aggregate (self-loop analytic) + bias + ELU + layer2 dots
__global__ void k_agg1f(const float* __restrict__ b1, int N) {
    int gw = (blockIdx.x * blockDim.x + threadIdx.x) >> 5;
    int lane = threadIdx.x & 31;
    if (gw >= N) return;
    int n = gw;
    int deg = min(g_ctr[n], CAP);
    const unsigned* crow = g_csr + (size_t)n * CAP;
    int myh = lane >> 2;

    float4 AD0 = *(const float4*)(g_ad1 + n * 8);
    float4 AD1 = *(const float4*)(g_ad1 + n * 8 + 4);
    float ad[8] = {AD0.x, AD0.y, AD0.z, AD0.w, AD1.x, AD1.y, AD1.z, AD1.w};
    float4 AN0 = *(const float4*)(g_as1 + n * 8);
    float4 AN1 = *(const float4*)(g_as1 + n * 8 + 4);
    float asn[8] = {AN0.x, AN0.y, AN0.z, AN0.w, AN1.x, AN1.y, AN1.z, AN1.w};

    float m[8], s[8];
    #pragma unroll
    for (int h = 0; h < 8; h++) { m[h] = -INFINITY; s[h] = 0.f; }

    for (int j = lane; j < deg; j += 32) {
        unsigned ent = crow[j];
        int src = (int)(ent & 0x7fffffffu);
        float msk = (ent & 0x80000000u) ? 0.f : 1.f;
        float4 A0 = *(const float4*)(g_as1 + src * 8);
        float4 A1 = *(const float4*)(g_as1 + src * 8 + 4);
        float as_[8] = {A0.x, A0.y, A0.z, A0.w, A1.x, A1.y, A1.z, A1.w};
        #pragma unroll
        for (int h = 0; h < 8; h++) {
            float t = as_[h] + ad[h];
            float e = t > 0.f ? t : NEG_SLOPE * t;
            float nm = fmaxf(m[h], e);
            s[h] = s[h] * __expf(m[h] - nm) + msk * __expf(e - nm);
            m[h] = nm;
        }
    }
    float myM = 0.f, myRS = 0.f, myE = 0.f;
    #pragma unroll
    for (int h = 0; h < 8; h++) {
        float M = m[h];
        #pragma unroll
        for (int o = 16; o > 0; o >>= 1) M = fmaxf(M, __shfl_xor_sync(0xffffffffu, M, o));
        float S = s[h] * __expf(m[h] - M);
        #pragma unroll
        for (int o = 16; o > 0; o >>= 1) S += __shfl_xor_sync(0xffffffffu, S, o);
        float t = asn[h] + ad[h];
        float e = t > 0.f ? t : NEG_SLOPE * t;
        float nm = fmaxf(M, e);
        S = S * __expf(M - nm) + __expf(e - nm);
        M = nm;
        if (h == myh) { myM = M; myRS = 1.f / (S + GAT_EPS); myE = e; }
    }

    int c0 = lane * 2;
    float adh = ad[0];
    #pragma unroll
    for (int h = 1; h < 8; h++) if (h == myh) adh = ad[h];
    float a0 = 0.f, a1 = 0.f;
    int deg4 = (deg + 3) & ~3;
    for (int j4 = 0; j4 < deg4; j4 += 4) {
        #pragma unroll
        for (int u = 0; u < 4; u++) {
            int j = j4 + u;
            unsigned ent = (j < deg) ? crow[j] : (0x80000000u | (unsigned)n);
            int src = (int)(ent & 0x7fffffffu);
            float msk = (ent & 0x80000000u) ? 0.f : 1.f;
            float t = g_as1[src * 8 + myh] + adh;
            float e = t > 0.f ? t : NEG_SLOPE * t;
            float w = msk * __expf(e - myM) * myRS;
            float2 v = *(const float2*)(g_h1 + (size_t)src * 64 + c0);
            a0 = fmaf(v.x, w, a0);
            a1 = fmaf(v.y, w, a1);
        }
    }
    {   // self-loop contribution
        float w = __expf(myE - myM) * myRS;
        float2 v = *(const float2*)(g_h1 + (size_t)n * 64 + c0);
        a0 = fmaf(v.x, w, a0);
        a1 = fmaf(v.y, w, a1);
    }
    float o0 = a0 + b1[c0], o1 = a1 + b1[c0 + 1];
    o0 = o0 > 0.f ? o0 : (__expf(o0) - 1.f);
    o1 = o1 > 0.f ? o1 : (__expf(o1) - 1.f);
    *(float2*)(g_h1a + (size_t)n * 64 + c0) = make_float2(o0, o1);

    #pragma unroll
    for (int h = 0; h < 8; h++) {
        float ps = o0 * g_vs[h * 64 + c0] + o1 * g_vs[h * 64 + c0 + 1];
        float pd = o0 * g_vd[h * 64 + c0] + o1 * g_vd[h * 64 + c0 + 1];
        #pragma unroll
        for (int o = 16; o > 0; o >>= 1) {
            ps += __shfl_xor_sync(0xffffffffu, ps, o);
            pd += __shfl_xor_sync(0xffffffffu, pd, o);
        }
        if (lane == 0) {
            g_as2[n * 8 + h] = ps;
            g_ad2[n * 8 + h] = pd;
        }
    }
}

// ---------------- merged layer-2: attention agg + GEMM + bias + log_softmax ----------------
#define AS_HSTR 68
#define AS_RSTR (8 * AS_HSTR)   // 544
#define ONODES 8
__global__ void __launch_bounds__(256)
k_agg2out(const float* __restrict__ W2, const float* __restrict__ bias,
          float* __restrict__ out, int N) {
    extern __shared__ float sm[];
    float* As = sm;                     // ONODES * 544
    float* O  = sm + ONODES * AS_RSTR;  // ONODES * 1024
    int tid = threadIdx.x, lane = tid & 31, wid = tid >> 5;
    int row0 = blockIdx.x * ONODES;

    // ---- phase A: warp `wid` aggregates node row0+wid across all 8 heads ----
    {
        int n = min(row0 + wid, N - 1);
        int deg = min(g_ctr[n], CAP);
        const unsigned* crow = g_csr + (size_t)n * CAP;
        float4 D0 = *(const float4*)(g_ad2 + n * 8);
        float4 D1 = *(const float4*)(g_ad2 + n * 8 + 4);
        float ad[8] = {D0.x, D0.y, D0.z, D0.w, D1.x, D1.y, D1.z, D1.w};
        float4 SN0 = *(const float4*)(g_as2 + n * 8);
        float4 SN1 = *(const float4*)(g_as2 + n * 8 + 4);
        float asn[8] = {SN0.x, SN0.y, SN0.z, SN0.w, SN1.x, SN1.y, SN1.z, SN1.w};

        float m[8], s[8];
        #pragma unroll
        for (int h = 0; h < 8; h++) { m[h] = -INFINITY; s[h] = 0.f; }
        for (int j = lane; j < deg; j += 32) {
            unsigned ent = crow[j];
            int src = (int)(ent & 0x7fffffffu);
            float msk = (ent & 0x80000000u) ? 0.f : 1.f;
            float4 A0 = *(const float4*)(g_as2 + src * 8);
            float4 A1 = *(const float4*)(g_as2 + src * 8 + 4);
            float as_[8] = {A0.x, A0.y, A0.z, A0.w, A1.x, A1.y, A1.z, A1.w};
            #pragma unroll
            for (int h = 0; h < 8; h++) {
                float t = as_[h] + ad[h];
                float e = t > 0.f ? t : NEG_SLOPE * t;
                float nm = fmaxf(m[h], e);
                s[h] = s[h] * __expf(m[h] - nm) + msk * __expf(e - nm);
                m[h] = nm;
            }
        }
        float M[8], rd[8], eself[8];
        #pragma unroll
        for (int h = 0; h < 8; h++) {
            float Mh = m[h];
            #pragma unroll
            for (int o = 16; o > 0; o >>= 1) Mh = fmaxf(Mh, __shfl_xor_sync(0xffffffffu, Mh, o));
            float Sh = s[h] * __expf(m[h] - Mh);
            #pragma unroll
            for (int o = 16; o > 0; o >>= 1) Sh += __shfl_xor_sync(0xffffffffu, Sh, o);
            float t = asn[h] + ad[h];
            float e = t > 0.f ? t : NEG_SLOPE * t;
            float nm = fmaxf(Mh, e);
            Sh = Sh * __expf(Mh - nm) + __expf(e - nm);
            M[h] = nm;
            rd[h] = 1.f / (Sh + GAT_EPS);
            eself[h] = e;
        }

        int c0 = lane * 2;
        float acc[16];
        #pragma unroll
        for (int i = 0; i < 16; i++) acc[i] = 0.f;

        for (int basej = 0; basej < deg; basej += 32) {
            int cnt = min(32, deg - basej);
            float w8[8];
            int srcl = n;            // lanes >= cnt: valid address, zero weight
            #pragma unroll
            for (int h = 0; h < 8; h++) w8[h] = 0.f;
            if (lane < cnt) {
                unsigned ent = crow[basej + lane];
                srcl = (int)(ent & 0x7fffffffu);
                float msk = (ent & 0x80000000u) ? 0.f : 1.f;
                float4 A0 = *(const float4*)(g_as2 + srcl * 8);
                float4 A1 = *(const float4*)(g_as2 + srcl * 8 + 4);
                float as_[8] = {A0.x, A0.y, A0.z, A0.w, A1.x, A1.y, A1.z, A1.w};
                #pragma unroll
                for (int h = 0; h < 8; h++) {
                    float t = as_[h] + ad[h];
                    float e = t > 0.f ? t : NEG_SLOPE * t;
                    w8[h] = msk * __expf(e - M[h]) * rd[h];
                }
            }
            // MLP-4 gather: padded lanes carry w=0, src=n (exact no-op)
            int cnt4 = (cnt + 3) & ~3;
            for (int j4 = 0; j4 < cnt4; j4 += 4) {
                #pragma unroll
                for (int u = 0; u < 4; u++) {
                    int jj = j4 + u;
                    int src = __shfl_sync(0xffffffffu, srcl, jj);
                    float2 v = *(const float2*)(g_h1a + (size_t)src * 64 + c0);
                    #pragma unroll
                    for (int h = 0; h < 8; h++) {
                        float w = __shfl_sync(0xffffffffu, w8[h], jj);
                        acc[h * 2 + 0] = fmaf(v.x, w, acc[h * 2 + 0]);
                        acc[h * 2 + 1] = fmaf(v.y, w, acc[h * 2 + 1]);
                    }
                }
            }
        }
        {   // self-loop
            float2 v = *(const float2*)(g_h1a + (size_t)n * 64 + c0);
            #pragma unroll
            for (int h = 0; h < 8; h++) {
                float w = __expf(eself[h] - M[h]) * rd[h];
                acc[h * 2 + 0] = fmaf(v.x, w, acc[h * 2 + 0]);
                acc[h * 2 + 1] = fmaf(v.y, w, acc[h * 2 + 1]);
            }
        }
        #pragma unroll
        for (int h = 0; h < 8; h++) {
            As[wid * AS_RSTR + h * AS_HSTR + c0]     = acc[h * 2 + 0];
            As[wid * AS_RSTR + h * AS_HSTR + c0 + 1] = acc[h * 2 + 1];
        }
    }
    __syncthreads();

    // ---- phase B: GEMM (8 rows x 1024 cols, K=64 per head) + bias ----
    // lane owns 4 CONTIGUOUS cols -> one LDG.128 of W2 per k (was 4x LDG.32)
    {
        int hg = wid;                 // 8 warps = 8 heads
        int cb = hg * 128 + lane * 4; // contiguous quad
        float4 acc2[8];
        #pragma unroll
        for (int r = 0; r < 8; r++) acc2[r] = make_float4(0.f, 0.f, 0.f, 0.f);
        const float* Wp = W2 + cb;
        const float* Ap = As + hg * AS_HSTR;
        #pragma unroll 4
        for (int k = 0; k < 64; k++) {
            float4 w = *(const float4*)(Wp + (size_t)k * 1024);
            #pragma unroll
            for (int r = 0; r < 8; r++) {
                float a = Ap[r * AS_RSTR + k];
                acc2[r].x = fmaf(a, w.x, acc2[r].x);
                acc2[r].y = fmaf(a, w.y, acc2[r].y);
                acc2[r].z = fmaf(a, w.z, acc2[r].z);
                acc2[r].w = fmaf(a, w.w, acc2[r].w);
            }
        }
        float4 bb = *(const float4*)(bias + cb);
        #pragma unroll
        for (int r = 0; r < 8; r++) {
            float4 o;
            o.x = acc2[r].x + bb.x;
            o.y = acc2[r].y + bb.y;
            o.z = acc2[r].z + bb.z;
            o.w = acc2[r].w + bb.w;
            *(float4*)(O + r * 1024 + cb) = o;
        }
    }
    __syncthreads();

    // ---- phase C: log_softmax, warp per row ----
    int n2 = row0 + wid;
    if (n2 < N) {
        const float4* Or = (const float4*)(O + wid * 1024);
        float m = -INFINITY;
        #pragma unroll
        for (int i = 0; i < 8; i++) {
            float4 xv = Or[lane + i * 32];
            m = fmaxf(m, fmaxf(fmaxf(xv.x, xv.y), fmaxf(xv.z, xv.w)));
        }
        #pragma unroll
        for (int o = 16; o > 0; o >>= 1) m = fmaxf(m, __shfl_xor_sync(0xffffffffu, m, o));
        float s = 0.f;
        #pragma unroll
        for (int i = 0; i < 8; i++) {
            float4 xv = Or[lane + i * 32];
            s += __expf(xv.x - m) + __expf(xv.y - m) + __expf(xv.z - m) + __expf(xv.w - m);
        }
        #pragma unroll
        for (int o = 16; o > 0; o >>= 1) s += __shfl_xor_sync(0xffffffffu, s, o);
        float lse = m + logf(s);
        float4* op = (float4*)(out + (size_t)n2 * 1024);
        #pragma unroll
        for (int i = 0; i < 8; i++) {
            float4 xv = Or[lane + i * 32];
            op[lane + i * 32] = make_float4(xv.x - lse, xv.y - lse, xv.z - lse, xv.w - lse);
        }
    }
}

// ---------------- launcher (round-12 fork/join structure) ----------------
extern "C" void kernel_launch(void* const* d_in, const int* in_sizes, int n_in,
                              void* d_out, int out_size) {
    const float* x   = (const float*)d_in[0];
    const int*   ei  = (const int*)d_in[1];
    const float* W1  = (const float*)d_in[2];
    const float* aS1 = (const float*)d_in[3];
    const float* aD1 = (const float*)d_in[4];
    const float* b1  = (const float*)d_in[5];
    const float* W2  = (const float*)d_in[6];
    const float* aS2 = (const float*)d_in[7];
    const float* aD2 = (const float*)d_in[8];
    const float* b2  = (const float*)d_in[9];
    float*       out = (float*)d_out;

    int N = in_sizes[0] / 128;
    int E = in_sizes[1] / 2;

    static cudaStream_t sB = nullptr;
    static cudaEvent_t evF = nullptr, evB = nullptr;
    static void* p_ctr = nullptr;
    static const int SMEM2 = (ONODES * AS_RSTR + ONODES * 1024) * 4;   // 50176
    if (!sB) {
        cudaStreamCreateWithFlags(&sB, cudaStreamNonBlocking);
        cudaEventCreateWithFlags(&evF, cudaEventDisableTiming);
        cudaEventCreateWithFlags(&evB, cudaEventDisableTiming);
        cudaGetSymbolAddress(&p_ctr, g_ctr);
        cudaFuncSetAttribute(k_agg2out, cudaFuncAttributeMaxDynamicSharedMemorySize, SMEM2);
    }

    // fork: GEMM1(+attn1+prep2) concurrent with CSR fill
    cudaEventRecord(evF, 0);
    cudaStreamWaitEvent(sB, evF, 0);
    k_gemm1f<<<(N + 15) / 16 + 1, 256, 0, sB>>>(x, W1, aS1, aD1, W2, aS2, aD2, N);
    cudaEventRecord(evB, sB);

    cudaMemsetAsync(p_ctr, 0, N * sizeof(int), 0);
    if ((E & 3) == 0) {
        k_fill4<<<(E / 4 + 255) / 256, 256>>>(ei, E, N);
    } else {
        k_fill<<<(E + 255) / 256, 256>>>(ei, E, N);
    }

    // join
    cudaStreamWaitEvent(0, evB, 0);
    k_agg1f  <<<(N * 32 + 255) / 256, 256>>>(b1, N);
    k_agg2out<<<(N + ONODES - 1) / ONODES, 256, SMEM2>>>(W2, b2, out, N);
}

// round 15
// speedup vs baseline: 1.1919x; 1.0405x over previous
#include <cuda_runtime.h>
#include <math.h>

#define NMAX 10000
#define EMAX 160000
#define CAP  96
#define NEG_SLOPE 0.2f
#define GAT_EPS 1e-16f

// ---------------- device scratch ----------------
__device__ int      g_ctr[NMAX];
__device__ unsigned g_csr[NMAX * CAP];            // src | (maskedBit<<31), bucketed
__device__ __align__(16) float g_h1[NMAX * 64];
__device__ __align__(16) float g_as1[NMAX * 8];
__device__ __align__(16) float g_ad1[NMAX * 8];
__device__ __align__(16) float g_h1a[NMAX * 64];
__device__ __align__(16) float g_vs[8 * 64];
__device__ __align__(16) float g_vd[8 * 64];
__device__ __align__(16) float g_as2[NMAX * 8];
__device__ __align__(16) float g_ad2[NMAX * 8];

// ---------------- CSR fill (bucketed, no scan) ----------------
__global__ void k_fill4(const int* __restrict__ ei, int E, int N) {
    int i = blockIdx.x * blockDim.x + threadIdx.x;
    int j = i * 4;
    if (j + 3 < E) {
        int4 s4 = ((const int4*)ei)[i];
        int4 d4 = ((const int4*)(ei + E))[i];
        int ss[4] = {s4.x, s4.y, s4.z, s4.w};
        int dd[4] = {d4.x, d4.y, d4.z, d4.w};
        #pragma unroll
        for (int t = 0; t < 4; t++) {
            int s = ss[t], d = dd[t];
            if ((unsigned)s >= (unsigned)N || (unsigned)d >= (unsigned)N) continue;
            unsigned ent = (unsigned)s | ((s == d) ? 0x80000000u : 0u);
            int pos = atomicAdd(&g_ctr[d], 1);
            if (pos < CAP) g_csr[d * CAP + pos] = ent;
        }
    } else {
        for (int t = j; t < E; t++) {
            int s = ei[t], d = ei[E + t];
            if ((unsigned)s >= (unsigned)N || (unsigned)d >= (unsigned)N) continue;
            unsigned ent = (unsigned)s | ((s == d) ? 0x80000000u : 0u);
            int pos = atomicAdd(&g_ctr[d], 1);
            if (pos < CAP) g_csr[d * CAP + pos] = ent;
        }
    }
}
__global__ void k_fill(const int* __restrict__ ei, int E, int N) {
    int i = blockIdx.x * blockDim.x + threadIdx.x;
    if (i >= E) return;
    int s = ei[i];
    int d = ei[E + i];
    if ((unsigned)s >= (unsigned)N || (unsigned)d >= (unsigned)N) return;
    unsigned ent = (unsigned)s | ((s == d) ? 0x80000000u : 0u);
    int pos = atomicAdd(&g_ctr[d], 1);
    if (pos < CAP) g_csr[d * CAP + pos] = ent;
}

// ---------------- layer 1 GEMM + attn dots + (folded) prep2 ----------------
__global__ void k_gemm1f(const float* __restrict__ x, const float* __restrict__ W1,
                         const float* __restrict__ asw, const float* __restrict__ adw,
                         const float* __restrict__ W2, const float* __restrict__ as2w,
                         const float* __restrict__ ad2w, int N) {
    if (blockIdx.x == gridDim.x - 1) {
        int tid = threadIdx.x;
        for (int idx = tid; idx < 512; idx += 256) {
            int h = idx >> 6, k = idx & 63;
            const float* wrow = W2 + (size_t)k * 1024 + h * 128;
            const float* sa = as2w + h * 128;
            const float* da = ad2w + h * 128;
            float s = 0.f, d = 0.f;
            #pragma unroll 4
            for (int c = 0; c < 128; c++) {
                float w = wrow[c];
                s = fmaf(w, sa[c], s);
                d = fmaf(w, da[c], d);
            }
            g_vs[h * 64 + k] = s;
            g_vd[h * 64 + k] = d;
        }
        return;
    }
    int col  = threadIdx.x & 63;
    int rs   = threadIdx.x >> 6;
    int row0 = blockIdx.x * 16 + rs * 4;
    const float* xp0 = x + (size_t)min(row0 + 0, N - 1) * 128;
    const float* xp1 = x + (size_t)min(row0 + 1, N - 1) * 128;
    const float* xp2 = x + (size_t)min(row0 + 2, N - 1) * 128;
    const float* xp3 = x + (size_t)min(row0 + 3, N - 1) * 128;
    float a[4] = {0.f, 0.f, 0.f, 0.f};
    #pragma unroll 4
    for (int k = 0; k < 128; k++) {
        float w = W1[k * 64 + col];
        a[0] = fmaf(xp0[k], w, a[0]);
        a[1] = fmaf(xp1[k], w, a[1]);
        a[2] = fmaf(xp2[k], w, a[2]);
        a[3] = fmaf(xp3[k], w, a[3]);
    }
    #pragma unroll
    for (int r = 0; r < 4; r++)
        if (row0 + r < N) g_h1[(size_t)(row0 + r) * 64 + col] = a[r];

    float ws = asw[col], wd = adw[col];
    #pragma unroll
    for (int r = 0; r < 4; r++) {
        float ps = a[r] * ws, pd = a[r] * wd;
        ps += __shfl_down_sync(0xffffffffu, ps, 4);
        pd += __shfl_down_sync(0xffffffffu, pd, 4);
        ps += __shfl_down_sync(0xffffffffu, ps, 2);
        pd += __shfl_down_sync(0xffffffffu, pd, 2);
        ps += __shfl_down_sync(0xffffffffu, ps, 1);
        pd += __shfl_down_sync(0xffffffffu, pd, 1);
        if ((col & 7) == 0 && row0 + r < N) {
            g_as1[(row0 + r) * 8 + (col >> 3)] = ps;
            g_ad1[(row0 + r) * 8 + (col >> 3)] = pd;
        }
    }
}

// one warp per node: layer1 softmax+aggregate (self-loop analytic) + bias + ELU + layer2 dots
__global__ void k_agg1f(const float* __restrict__ b1, int N) {
    int gw = (blockIdx.x * blockDim.x + threadIdx.x) >> 5;
    int lane = threadIdx.x & 31;
    if (gw >= N) return;
    int n = gw;
    int deg = min(g_ctr[n], CAP);
    const unsigned* crow = g_csr + (size_t)n * CAP;
    int myh = lane >> 2;

    float4 AD0 = *(const float4*)(g_ad1 + n * 8);
    float4 AD1 = *(const float4*)(g_ad1 + n * 8 + 4);
    float ad[8] = {AD0.x, AD0.y, AD0.z, AD0.w, AD1.x, AD1.y, AD1.z, AD1.w};
    float4 AN0 = *(const float4*)(g_as1 + n * 8);
    float4 AN1 = *(const float4*)(g_as1 + n * 8 + 4);
    float asn[8] = {AN0.x, AN0.y, AN0.z, AN0.w, AN1.x, AN1.y, AN1.z, AN1.w};

    float m[8], s[8];
    #pragma unroll
    for (int h = 0; h < 8; h++) { m[h] = -INFINITY; s[h] = 0.f; }

    for (int j = lane; j < deg; j += 32) {
        unsigned ent = crow[j];
        int src = (int)(ent & 0x7fffffffu);
        float msk = (ent & 0x80000000u) ? 0.f : 1.f;
        float4 A0 = *(const float4*)(g_as1 + src * 8);
        float4 A1 = *(const float4*)(g_as1 + src * 8 + 4);
        float as_[8] = {A0.x, A0.y, A0.z, A0.w, A1.x, A1.y, A1.z, A1.w};
        #pragma unroll
        for (int h = 0; h < 8; h++) {
            float t = as_[h] + ad[h];
            float e = t > 0.f ? t : NEG_SLOPE * t;
            float nm = fmaxf(m[h], e);
            s[h] = s[h] * __expf(m[h] - nm) + msk * __expf(e - nm);
            m[h] = nm;
        }
    }
    float myM = 0.f, myRS = 0.f, myE = 0.f;
    #pragma unroll
    for (int h = 0; h < 8; h++) {
        float M = m[h];
        #pragma unroll
        for (int o = 16; o > 0; o >>= 1) M = fmaxf(M, __shfl_xor_sync(0xffffffffu, M, o));
        float S = s[h] * __expf(m[h] - M);
        #pragma unroll
        for (int o = 16; o > 0; o >>= 1) S += __shfl_xor_sync(0xffffffffu, S, o);
        float t = asn[h] + ad[h];
        float e = t > 0.f ? t : NEG_SLOPE * t;
        float nm = fmaxf(M, e);
        S = S * __expf(M - nm) + __expf(e - nm);
        M = nm;
        if (h == myh) { myM = M; myRS = 1.f / (S + GAT_EPS); myE = e; }
    }

    int c0 = lane * 2;
    float adh = ad[0];
    #pragma unroll
    for (int h = 1; h < 8; h++) if (h == myh) adh = ad[h];
    float a0 = 0.f, a1 = 0.f;
    int deg4 = (deg + 3) & ~3;
    for (int j4 = 0; j4 < deg4; j4 += 4) {
        #pragma unroll
        for (int u = 0; u < 4; u++) {
            int j = j4 + u;
            unsigned ent = (j < deg) ? crow[j] : (0x80000000u | (unsigned)n);
            int src = (int)(ent & 0x7fffffffu);
            float msk = (ent & 0x80000000u) ? 0.f : 1.f;
            float t = g_as1[src * 8 + myh] + adh;
            float e = t > 0.f ? t : NEG_SLOPE * t;
            float w = msk * __expf(e - myM) * myRS;
            float2 v = *(const float2*)(g_h1 + (size_t)src * 64 + c0);
            a0 = fmaf(v.x, w, a0);
            a1 = fmaf(v.y, w, a1);
        }
    }
    {   // self-loop contribution
        float w = __expf(myE - myM) * myRS;
        float2 v = *(const float2*)(g_h1 + (size_t)n * 64 + c0);
        a0 = fmaf(v.x, w, a0);
        a1 = fmaf(v.y, w, a1);
    }
    float o0 = a0 + b1[c0], o1 = a1 + b1[c0 + 1];
    o0 = o0 > 0.f ? o0 : (__expf(o0) - 1.f);
    o1 = o1 > 0.f ? o1 : (__expf(o1) - 1.f);
    *(float2*)(g_h1a + (size_t)n * 64 + c0) = make_float2(o0, o1);

    #pragma unroll
    for (int h = 0; h < 8; h++) {
        float ps = o0 * g_vs[h * 64 + c0] + o1 * g_vs[h * 64 + c0 + 1];
        float pd = o0 * g_vd[h * 64 + c0] + o1 * g_vd[h * 64 + c0 + 1];
        #pragma unroll
        for (int o = 16; o > 0; o >>= 1) {
            ps += __shfl_xor_sync(0xffffffffu, ps, o);
            pd += __shfl_xor_sync(0xffffffffu, pd, o);
        }
        if (lane == 0) {
            g_as2[n * 8 + h] = ps;
            g_ad2[n * 8 + h] = pd;
        }
    }
}

// ---------------- merged layer-2: attention agg + GEMM + bias + log_softmax ----------------
// Self-loop handled as a VIRTUAL EDGE (index deg, src=n, mask=1).
// Softmax stats (M, 1/S) live in smem, not registers -> lower reg pressure.
#define AS_HSTR 68
#define AS_RSTR (8 * AS_HSTR)   // 544
#define ONODES 8
__global__ void __launch_bounds__(256)
k_agg2out(const float* __restrict__ W2, const float* __restrict__ bias,
          float* __restrict__ out, int N) {
    extern __shared__ float sm[];
    float* As  = sm;                        // ONODES * 544
    float* O   = sm + ONODES * AS_RSTR;     // ONODES * 1024
    float* s_M = sm + ONODES * AS_RSTR + ONODES * 1024;        // 64
    float* s_R = s_M + 64;                                      // 64
    int tid = threadIdx.x, lane = tid & 31, wid = tid >> 5;
    int row0 = blockIdx.x * ONODES;

    // ---- phase A: warp `wid` aggregates node row0+wid across all 8 heads ----
    {
        int n = min(row0 + wid, N - 1);
        int deg = min(g_ctr[n], CAP);
        int deg1 = deg + 1;                  // + virtual self edge
        const unsigned* crow = g_csr + (size_t)n * CAP;
        float4 D0 = *(const float4*)(g_ad2 + n * 8);
        float4 D1 = *(const float4*)(g_ad2 + n * 8 + 4);
        float ad[8] = {D0.x, D0.y, D0.z, D0.w, D1.x, D1.y, D1.z, D1.w};

        float m[8], s[8];
        #pragma unroll
        for (int h = 0; h < 8; h++) { m[h] = -INFINITY; s[h] = 0.f; }
        for (int j = lane; j < deg1; j += 32) {
            unsigned ent = (j < deg) ? crow[j] : (unsigned)n;   // self: mask bit clear
            int src = (int)(ent & 0x7fffffffu);
            float msk = (ent & 0x80000000u) ? 0.f : 1.f;
            float4 A0 = *(const float4*)(g_as2 + src * 8);
            float4 A1 = *(const float4*)(g_as2 + src * 8 + 4);
            float as_[8] = {A0.x, A0.y, A0.z, A0.w, A1.x, A1.y, A1.z, A1.w};
            #pragma unroll
            for (int h = 0; h < 8; h++) {
                float t = as_[h] + ad[h];
                float e = t > 0.f ? t : NEG_SLOPE * t;
                float nm = fmaxf(m[h], e);
                s[h] = s[h] * __expf(m[h] - nm) + msk * __expf(e - nm);
                m[h] = nm;
            }
        }
        #pragma unroll
        for (int h = 0; h < 8; h++) {
            float Mh = m[h];
            #pragma unroll
            for (int o = 16; o > 0; o >>= 1) Mh = fmaxf(Mh, __shfl_xor_sync(0xffffffffu, Mh, o));
            float Sh = s[h] * __expf(m[h] - Mh);
            #pragma unroll
            for (int o = 16; o > 0; o >>= 1) Sh += __shfl_xor_sync(0xffffffffu, Sh, o);
            if (lane == 0) {
                s_M[wid * 8 + h] = Mh;
                s_R[wid * 8 + h] = 1.f / (Sh + GAT_EPS);
            }
        }
        __syncwarp();

        int c0 = lane * 2;
        float acc[16];
        #pragma unroll
        for (int i = 0; i < 16; i++) acc[i] = 0.f;

        for (int basej = 0; basej < deg1; basej += 32) {
            int cnt = min(32, deg1 - basej);
            float w8[8];
            int srcl = n;            // lanes >= cnt: valid address, zero weight
            #pragma unroll
            for (int h = 0; h < 8; h++) w8[h] = 0.f;
            if (lane < cnt) {
                int j = basej + lane;
                unsigned ent = (j < deg) ? crow[j] : (unsigned)n;
                srcl = (int)(ent & 0x7fffffffu);
                float msk = (ent & 0x80000000u) ? 0.f : 1.f;
                float4 A0 = *(const float4*)(g_as2 + srcl * 8);
                float4 A1 = *(const float4*)(g_as2 + srcl * 8 + 4);
                float as_[8] = {A0.x, A0.y, A0.z, A0.w, A1.x, A1.y, A1.z, A1.w};
                #pragma unroll
                for (int h = 0; h < 8; h++) {
                    float t = as_[h] + ad[h];
                    float e = t > 0.f ? t : NEG_SLOPE * t;
                    w8[h] = msk * __expf(e - s_M[wid * 8 + h]) * s_R[wid * 8 + h];
                }
            }
            // MLP-4 gather: padded lanes carry w=0, src=n (exact no-op)
            int cnt4 = (cnt + 3) & ~3;
            for (int j4 = 0; j4 < cnt4; j4 += 4) {
                #pragma unroll
                for (int u = 0; u < 4; u++) {
                    int jj = j4 + u;
                    int src = __shfl_sync(0xffffffffu, srcl, jj);
                    float2 v = *(const float2*)(g_h1a + (size_t)src * 64 + c0);
                    #pragma unroll
                    for (int h = 0; h < 8; h++) {
                        float w = __shfl_sync(0xffffffffu, w8[h], jj);
                        acc[h * 2 + 0] = fmaf(v.x, w, acc[h * 2 + 0]);
                        acc[h * 2 + 1] = fmaf(v.y, w, acc[h * 2 + 1]);
                    }
                }
            }
        }
        #pragma unroll
        for (int h = 0; h < 8; h++) {
            As[wid * AS_RSTR + h * AS_HSTR + c0]     = acc[h * 2 + 0];
            As[wid * AS_RSTR + h * AS_HSTR + c0 + 1] = acc[h * 2 + 1];
        }
    }
    __syncthreads();

    // ---- phase B: GEMM (8 rows x 1024 cols, K=64 per head) + bias ----
    {
        int hg = wid;          // 8 warps = 8 heads
        int q = lane;
        int cb = hg * 128 + q;
        float acc2[8][4];
        #pragma unroll
        for (int r = 0; r < 8; r++)
            #pragma unroll
            for (int c = 0; c < 4; c++) acc2[r][c] = 0.f;
        const float* Wp = W2 + cb;
        const float* Ap = As + hg * AS_HSTR;
        #pragma unroll 4
        for (int k = 0; k < 64; k++) {
            const float* wk = Wp + (size_t)k * 1024;
            float w0 = wk[0], w1 = wk[32], w2 = wk[64], w3 = wk[96];
            #pragma unroll
            for (int r = 0; r < 8; r++) {
                float a = Ap[r * AS_RSTR + k];
                acc2[r][0] = fmaf(a, w0, acc2[r][0]);
                acc2[r][1] = fmaf(a, w1, acc2[r][1]);
                acc2[r][2] = fmaf(a, w2, acc2[r][2]);
                acc2[r][3] = fmaf(a, w3, acc2[r][3]);
            }
        }
        float bb0 = bias[cb], bb1 = bias[cb + 32], bb2 = bias[cb + 64], bb3 = bias[cb + 96];
        #pragma unroll
        for (int r = 0; r < 8; r++) {
            float* Orow = O + r * 1024 + cb;
            Orow[0]  = acc2[r][0] + bb0;
            Orow[32] = acc2[r][1] + bb1;
            Orow[64] = acc2[r][2] + bb2;
            Orow[96] = acc2[r][3] + bb3;
        }
    }
    __syncthreads();

    // ---- phase C: log_softmax, warp per row ----
    int n2 = row0 + wid;
    if (n2 < N) {
        const float4* Or = (const float4*)(O + wid * 1024);
        float m = -INFINITY;
        #pragma unroll
        for (int i = 0; i < 8; i++) {
            float4 xv = Or[lane + i * 32];
            m = fmaxf(m, fmaxf(fmaxf(xv.x, xv.y), fmaxf(xv.z, xv.w)));
        }
        #pragma unroll
        for (int o = 16; o > 0; o >>= 1) m = fmaxf(m, __shfl_xor_sync(0xffffffffu, m, o));
        float s = 0.f;
        #pragma unroll
        for (int i = 0; i < 8; i++) {
            float4 xv = Or[lane + i * 32];
            s += __expf(xv.x - m) + __expf(xv.y - m) + __expf(xv.z - m) + __expf(xv.w - m);
        }
        #pragma unroll
        for (int o = 16; o > 0; o >>= 1) s += __shfl_xor_sync(0xffffffffu, s, o);
        float lse = m + logf(s);
        float4* op = (float4*)(out + (size_t)n2 * 1024);
        #pragma unroll
        for (int i = 0; i < 8; i++) {
            float4 xv = Or[lane + i * 32];
            op[lane + i * 32] = make_float4(xv.x - lse, xv.y - lse, xv.z - lse, xv.w - lse);
        }
    }
}

// ---------------- launcher (round-12 fork/join structure) ----------------
extern "C" void kernel_launch(void* const* d_in, const int* in_sizes, int n_in,
                              void* d_out, int out_size) {
    const float* x   = (const float*)d_in[0];
    const int*   ei  = (const int*)d_in[1];
    const float* W1  = (const float*)d_in[2];
    const float* aS1 = (const float*)d_in[3];
    const float* aD1 = (const float*)d_in[4];
    const float* b1  = (const float*)d_in[5];
    const float* W2  = (const float*)d_in[6];
    const float* aS2 = (const float*)d_in[7];
    const float* aD2 = (const float*)d_in[8];
    const float* b2  = (const float*)d_in[9];
    float*       out = (float*)d_out;

    int N = in_sizes[0] / 128;
    int E = in_sizes[1] / 2;

    static cudaStream_t sB = nullptr;
    static cudaEvent_t evF = nullptr, evB = nullptr;
    static void* p_ctr = nullptr;
    static const int SMEM2 = (ONODES * AS_RSTR + ONODES * 1024 + 128) * 4;   // 50688
    if (!sB) {
        cudaStreamCreateWithFlags(&sB, cudaStreamNonBlocking);
        cudaEventCreateWithFlags(&evF, cudaEventDisableTiming);
        cudaEventCreateWithFlags(&evB, cudaEventDisableTiming);
        cudaGetSymbolAddress(&p_ctr, g_ctr);
        cudaFuncSetAttribute(k_agg2out, cudaFuncAttributeMaxDynamicSharedMemorySize, SMEM2);
    }

    // fork: GEMM1(+attn1+prep2) concurrent with CSR fill
    cudaEventRecord(evF, 0);
    cudaStreamWaitEvent(sB, evF, 0);
    k_gemm1f<<<(N + 15) / 16 + 1, 256, 0, sB>>>(x, W1, aS1, aD1, W2, aS2, aD2, N);
    cudaEventRecord(evB, sB);

    cudaMemsetAsync(p_ctr, 0, N * sizeof(int), 0);
    if ((E & 3) == 0) {
        k_fill4<<<(E / 4 + 255) / 256, 256>>>(ei, E, N);
    } else {
        k_fill<<<(E + 255) / 256, 256>>>(ei, E, N);
    }

    // join
    cudaStreamWaitEvent(0, evB, 0);
    k_agg1f  <<<(N * 32 + 255) / 256, 256>>>(b1, N);
    k_agg2out<<<(N + ONODES - 1) / ONODES, 256, SMEM2>>>(W2, b2, out, N);
}